// round 14
// baseline (speedup 1.0000x reference)
#include <cuda_runtime.h>
#include <cuda_fp16.h>

#define N_TOTAL 65536
#define NNZ (16 * N_TOTAL)
#define STEPS 16
#define MAXW 64
#define NGROUP (MAXW / 4)           // 16 uint4 groups per row
#define TB 256
#define PARTS 4
#define ROWS_PER_BLK (TB / PARTS)   // 64 rows per block

// ---------------------------------------------------------------------------
// Device-global scratch (allocation-free, zero-initialized at module load).
__device__ float2   g_U[2][N_TOTAL];          // interleaved (Ur,Ui) ping-pong
__device__ unsigned g_cnt[N_TOTAL];           // MONOTONIC fill cursor per row
__device__ unsigned g_base[N_TOTAL];          // cursor snapshot from prev launch
__device__ uint4    g_q4[NGROUP * N_TOTAL];   // packed ELL: [slot_group][row],
                                              // u32 = {f16 val, u16 col}.
                                              // Tail slots stay 0 forever
                                              // (fill writes only [0,cnt)).

// ---------------------------------------------------------------------------
// K1: fused fill + U0 pack. Epoch trick: pos = atomicAdd(cnt) - base, where
// base is the snapshot taken at the end of the previous launch (0 initially),
// so no per-launch cnt reset pass is needed.
__device__ __forceinline__ void put(int r, int c, float av) {
    unsigned pos = atomicAdd(&g_cnt[r], 1u) - g_base[r];
    unsigned packed = (unsigned)(c & 0xFFFF)
                    | ((unsigned)__half_as_ushort(__float2half_rn(av)) << 16);
    ((unsigned*)g_q4)[(((pos >> 2) * N_TOTAL + (unsigned)r) << 2) + (pos & 3)] = packed;
}

__global__ __launch_bounds__(TB)
void fill_kernel(const float4* __restrict__ A4,
                 const int4* __restrict__ R4,
                 const int4* __restrict__ C4,
                 const float* __restrict__ Ur0,
                 const float* __restrict__ Ui0, float dz) {
    int i = blockIdx.x * blockDim.x + threadIdx.x;   // 0 .. NNZ/8-1 (=131072)
    if (i < N_TOTAL)                                 // fold U0 packing in
        g_U[0][i] = make_float2(Ur0[i], Ui0[i]);
    if (i >= NNZ / 8) return;
    float4 a0 = A4[2 * i], a1 = A4[2 * i + 1];
    int4   r0 = R4[2 * i], r1 = R4[2 * i + 1];
    int4   c0 = C4[2 * i], c1 = C4[2 * i + 1];
    put(r0.x, c0.x, a0.x * dz);
    put(r0.y, c0.y, a0.y * dz);
    put(r0.z, c0.z, a0.z * dz);
    put(r0.w, c0.w, a0.w * dz);
    put(r1.x, c1.x, a1.x * dz);
    put(r1.y, c1.y, a1.y * dz);
    put(r1.z, c1.z, a1.z * dz);
    put(r1.w, c1.w, a1.w * dz);
}

// ---------------------------------------------------------------------------
// K2: one Euler step. 4 lanes per row; lane `part` handles slot-groups
// part, part+4, ... One coalesced 16B load -> 4 independent gathers.
// No tail masks: unwritten tail slots are all-zero (val=0 contributes 0).
// FINAL also writes planar output and snapshots g_base for the next launch.
template <bool FINAL>
__global__ __launch_bounds__(TB)
void step_kernel(int src, float* __restrict__ out) {
    __shared__ float s_r[PARTS][ROWS_PER_BLK];
    __shared__ float s_i[PARTS][ROWS_PER_BLK];

    const int part = threadIdx.x >> 6;               // 0..3
    const int lr   = threadIdx.x & (ROWS_PER_BLK - 1);
    const int r    = blockIdx.x * ROWS_PER_BLK + lr;

    const float2* __restrict__ U = g_U[src];
    const unsigned raw  = g_cnt[r];
    const unsigned cnt  = raw - g_base[r];

    float sr = 0.f, si = 0.f;
    #pragma unroll 2
    for (unsigned g = part; 4 * g < cnt; g += PARTS) {
        uint4 q = g_q4[g * N_TOTAL + r];
        float2 u0 = __ldg(&U[q.x & 0xFFFFu]);
        float2 u1 = __ldg(&U[q.y & 0xFFFFu]);
        float2 u2 = __ldg(&U[q.z & 0xFFFFu]);
        float2 u3 = __ldg(&U[q.w & 0xFFFFu]);
        float v0 = __half2float(__ushort_as_half((unsigned short)(q.x >> 16)));
        float v1 = __half2float(__ushort_as_half((unsigned short)(q.y >> 16)));
        float v2 = __half2float(__ushort_as_half((unsigned short)(q.z >> 16)));
        float v3 = __half2float(__ushort_as_half((unsigned short)(q.w >> 16)));
        sr = fmaf(v0, u0.y, sr);  si = fmaf(v0, u0.x, si);
        sr = fmaf(v1, u1.y, sr);  si = fmaf(v1, u1.x, si);
        sr = fmaf(v2, u2.y, sr);  si = fmaf(v2, u2.x, si);
        sr = fmaf(v3, u3.y, sr);  si = fmaf(v3, u3.x, si);
    }
    s_r[part][lr] = sr;
    s_i[part][lr] = si;
    __syncthreads();

    if (part == 0) {
        float tr = s_r[0][lr] + s_r[1][lr] + s_r[2][lr] + s_r[3][lr];
        float ti = s_i[0][lr] + s_i[1][lr] + s_i[2][lr] + s_i[3][lr];
        float2 mine = U[r];
        float2 nxt = make_float2(mine.x - tr, mine.y + ti);
        g_U[src ^ 1][r] = nxt;
        if (FINAL) {
            out[r]           = nxt.x;
            out[N_TOTAL + r] = nxt.y;
            g_base[r] = raw;                 // epoch snapshot for next launch
        }
    }
}

// ---------------------------------------------------------------------------
extern "C" void kernel_launch(void* const* d_in, const int* in_sizes, int n_in,
                              void* d_out, int out_size) {
    const float* A_vals  = (const float*)d_in[0];
    const int*   row_idx = (const int*)d_in[1];
    const int*   col_idx = (const int*)d_in[2];
    const float* Ur0     = (const float*)d_in[3];
    const float* Ui0     = (const float*)d_in[4];
    const float dz = 1.0f / (float)STEPS;

    fill_kernel<<<(NNZ / 8 + TB - 1) / TB, TB>>>(
        (const float4*)A_vals, (const int4*)row_idx, (const int4*)col_idx,
        Ur0, Ui0, dz);

    const int grid = N_TOTAL / ROWS_PER_BLK;         // 1024 blocks
    int src = 0;
    for (int s = 0; s < STEPS - 1; s++) {
        step_kernel<false><<<grid, TB>>>(src, nullptr);
        src ^= 1;
    }
    step_kernel<true><<<grid, TB>>>(src, (float*)d_out);
}

// round 16
// speedup vs baseline: 1.5439x; 1.5439x over previous
#include <cuda_runtime.h>
#include <cuda_fp16.h>

#define N_TOTAL 65536
#define NNZ (16 * N_TOTAL)
#define STEPS 16
#define MAXW 64
#define NGROUP (MAXW / 4)           // 16 uint4 groups per row
#define TB 256
#define PARTS 4
#define ROWS_PER_BLK (TB / PARTS)   // 64 rows per block

// ---------------------------------------------------------------------------
// Device-global scratch (allocation-free, zero-initialized at module load).
// g_cnt is left at ZERO by the FINAL step kernel of each launch, so no init
// pass is needed (statics start zero; every launch goes 0 -> 16 -> 0).
// g_q4 tail slots (>= cnt) are NEVER written: they stay zero from static
// initialization, and zero fp16 val bits contribute exactly 0 to the sums.
__device__ float2   g_U[2][N_TOTAL];          // interleaved (Ur,Ui) ping-pong
__device__ unsigned g_cnt[N_TOTAL];           // per-row fill cursor (self-reset)
__device__ uint4    g_q4[NGROUP * N_TOTAL];   // packed ELL: [slot_group][row],
                                              // u32 = {f16 val, u16 col}

// ---------------------------------------------------------------------------
// K1: fused fill + U0 pack (its grid already spans > N_TOTAL threads).
__device__ __forceinline__ void put(int r, int c, float av) {
    unsigned pos = atomicAdd(&g_cnt[r], 1u);
    unsigned packed = (unsigned)(c & 0xFFFF)
                    | ((unsigned)__half_as_ushort(__float2half_rn(av)) << 16);
    ((unsigned*)g_q4)[(((pos >> 2) * N_TOTAL + (unsigned)r) << 2) + (pos & 3)] = packed;
}

__global__ __launch_bounds__(TB)
void fill_kernel(const float4* __restrict__ A4,
                 const int4* __restrict__ R4,
                 const int4* __restrict__ C4,
                 const float* __restrict__ Ur0,
                 const float* __restrict__ Ui0, float dz) {
    int i = blockIdx.x * blockDim.x + threadIdx.x;   // 0 .. NNZ/8-1 (=131072)
    if (i < N_TOTAL)                                 // fold U0 packing in
        g_U[0][i] = make_float2(Ur0[i], Ui0[i]);
    if (i >= NNZ / 8) return;
    float4 a0 = A4[2 * i], a1 = A4[2 * i + 1];
    int4   r0 = R4[2 * i], r1 = R4[2 * i + 1];
    int4   c0 = C4[2 * i], c1 = C4[2 * i + 1];
    put(r0.x, c0.x, a0.x * dz);
    put(r0.y, c0.y, a0.y * dz);
    put(r0.z, c0.z, a0.z * dz);
    put(r0.w, c0.w, a0.w * dz);
    put(r1.x, c1.x, a1.x * dz);
    put(r1.y, c1.y, a1.y * dz);
    put(r1.z, c1.z, a1.z * dz);
    put(r1.w, c1.w, a1.w * dz);
}

// ---------------------------------------------------------------------------
// K2: one Euler step. 4 lanes per row; lane `part` handles slot-groups
// part, part+4, ... One coalesced 16B load -> 4 independent gathers.
// No tail masks (tail slots are all-zero). FINAL also writes planar output
// and resets g_cnt for the next graph replay.
template <bool FINAL>
__global__ __launch_bounds__(TB)
void step_kernel(int src, float* __restrict__ out) {
    __shared__ float s_r[PARTS][ROWS_PER_BLK];
    __shared__ float s_i[PARTS][ROWS_PER_BLK];

    const int part = threadIdx.x >> 6;               // 0..3
    const int lr   = threadIdx.x & (ROWS_PER_BLK - 1);
    const int r    = blockIdx.x * ROWS_PER_BLK + lr;

    const float2* __restrict__ U = g_U[src];
    const unsigned cnt = g_cnt[r];

    float sr = 0.f, si = 0.f;
    for (unsigned g = part; 4 * g < cnt; g += PARTS) {
        uint4 q = g_q4[g * N_TOTAL + r];
        float2 u0 = __ldg(&U[q.x & 0xFFFFu]);
        float2 u1 = __ldg(&U[q.y & 0xFFFFu]);
        float2 u2 = __ldg(&U[q.z & 0xFFFFu]);
        float2 u3 = __ldg(&U[q.w & 0xFFFFu]);
        float v0 = __half2float(__ushort_as_half((unsigned short)(q.x >> 16)));
        float v1 = __half2float(__ushort_as_half((unsigned short)(q.y >> 16)));
        float v2 = __half2float(__ushort_as_half((unsigned short)(q.z >> 16)));
        float v3 = __half2float(__ushort_as_half((unsigned short)(q.w >> 16)));
        sr = fmaf(v0, u0.y, sr);  si = fmaf(v0, u0.x, si);
        sr = fmaf(v1, u1.y, sr);  si = fmaf(v1, u1.x, si);
        sr = fmaf(v2, u2.y, sr);  si = fmaf(v2, u2.x, si);
        sr = fmaf(v3, u3.y, sr);  si = fmaf(v3, u3.x, si);
    }
    s_r[part][lr] = sr;
    s_i[part][lr] = si;
    __syncthreads();

    if (part == 0) {
        float tr = s_r[0][lr] + s_r[1][lr] + s_r[2][lr] + s_r[3][lr];
        float ti = s_i[0][lr] + s_i[1][lr] + s_i[2][lr] + s_i[3][lr];
        float2 mine = U[r];
        float2 nxt = make_float2(mine.x - tr, mine.y + ti);
        g_U[src ^ 1][r] = nxt;
        if (FINAL) {
            out[r]           = nxt.x;
            out[N_TOTAL + r] = nxt.y;
            g_cnt[r] = 0;                    // self-reset for next replay
        }
    }
}

// ---------------------------------------------------------------------------
extern "C" void kernel_launch(void* const* d_in, const int* in_sizes, int n_in,
                              void* d_out, int out_size) {
    const float* A_vals  = (const float*)d_in[0];
    const int*   row_idx = (const int*)d_in[1];
    const int*   col_idx = (const int*)d_in[2];
    const float* Ur0     = (const float*)d_in[3];
    const float* Ui0     = (const float*)d_in[4];
    const float dz = 1.0f / (float)STEPS;

    fill_kernel<<<(NNZ / 8 + TB - 1) / TB, TB>>>(
        (const float4*)A_vals, (const int4*)row_idx, (const int4*)col_idx,
        Ur0, Ui0, dz);

    const int grid = N_TOTAL / ROWS_PER_BLK;         // 1024 blocks
    int src = 0;
    for (int s = 0; s < STEPS - 1; s++) {
        step_kernel<false><<<grid, TB>>>(src, nullptr);
        src ^= 1;
    }
    step_kernel<true><<<grid, TB>>>(src, (float*)d_out);
}

// round 17
// speedup vs baseline: 1.6095x; 1.0425x over previous
#include <cuda_runtime.h>
#include <cuda_fp16.h>

#define N_TOTAL 65536
#define NNZ (16 * N_TOTAL)
#define STEPS 16
#define MAXW 64
#define NGROUP (MAXW / 4)           // 16 uint4 groups per row
#define TB 256
#define PARTS 4

// ---------------------------------------------------------------------------
// Device-global scratch (allocation-free, zero-initialized at module load).
// g_cnt self-resets (FINAL step writes 0), so no init pass is needed.
// Layout of g_q4 (uint4 units):
//   slots 0..15 of row r ("main"):      g_q4[r*4 + group]          (64B/row)
//   slots 16+  ("overflow", ELL-style): g_q4[4*N + (group-4)*N + r]
// Unwritten slots stay zero forever: packed=0 -> col 0, fp16 val 0 ->
// gather U[0] (warp-uniform broadcast) * 0 == exact 0 contribution.
__device__ float2   g_U[2][N_TOTAL];          // interleaved (Ur,Ui) ping-pong
__device__ unsigned g_cnt[N_TOTAL];           // per-row fill cursor (self-reset)
__device__ uint4    g_q4[NGROUP * N_TOTAL];   // packed: u32 = {f16 val, u16 col}

// ---------------------------------------------------------------------------
// K1: fused fill + U0 pack.
__device__ __forceinline__ void put(int r, int c, float av) {
    unsigned pos = atomicAdd(&g_cnt[r], 1u);
    unsigned packed = (unsigned)(c & 0xFFFF)
                    | ((unsigned)__half_as_ushort(__float2half_rn(av)) << 16);
    unsigned idx = (pos < 16u)
        ? ((unsigned)r * 16u + pos)                                    // main
        : (16u * N_TOTAL + ((pos >> 2) - 4u) * (4u * N_TOTAL)
           + (unsigned)r * 4u + (pos & 3u));                           // ovf
    ((unsigned*)g_q4)[idx] = packed;
}

__global__ __launch_bounds__(TB)
void fill_kernel(const float4* __restrict__ A4,
                 const int4* __restrict__ R4,
                 const int4* __restrict__ C4,
                 const float* __restrict__ Ur0,
                 const float* __restrict__ Ui0, float dz) {
    int i = blockIdx.x * blockDim.x + threadIdx.x;   // 0 .. NNZ/8-1 (=131072)
    if (i < N_TOTAL)                                 // fold U0 packing in
        g_U[0][i] = make_float2(Ur0[i], Ui0[i]);
    if (i >= NNZ / 8) return;
    float4 a0 = A4[2 * i], a1 = A4[2 * i + 1];
    int4   r0 = R4[2 * i], r1 = R4[2 * i + 1];
    int4   c0 = C4[2 * i], c1 = C4[2 * i + 1];
    put(r0.x, c0.x, a0.x * dz);
    put(r0.y, c0.y, a0.y * dz);
    put(r0.z, c0.z, a0.z * dz);
    put(r0.w, c0.w, a0.w * dz);
    put(r1.x, c1.x, a1.x * dz);
    put(r1.y, c1.y, a1.y * dz);
    put(r1.z, c1.z, a1.z * dz);
    put(r1.w, c1.w, a1.w * dz);
}

// ---------------------------------------------------------------------------
__device__ __forceinline__ void accum4(uint4 q, const float2* __restrict__ U,
                                       float& sr, float& si) {
    float2 u0 = __ldg(&U[q.x & 0xFFFFu]);
    float2 u1 = __ldg(&U[q.y & 0xFFFFu]);
    float2 u2 = __ldg(&U[q.z & 0xFFFFu]);
    float2 u3 = __ldg(&U[q.w & 0xFFFFu]);
    float v0 = __half2float(__ushort_as_half((unsigned short)(q.x >> 16)));
    float v1 = __half2float(__ushort_as_half((unsigned short)(q.y >> 16)));
    float v2 = __half2float(__ushort_as_half((unsigned short)(q.z >> 16)));
    float v3 = __half2float(__ushort_as_half((unsigned short)(q.w >> 16)));
    sr = fmaf(v0, u0.y, sr);  si = fmaf(v0, u0.x, si);
    sr = fmaf(v1, u1.y, sr);  si = fmaf(v1, u1.x, si);
    sr = fmaf(v2, u2.y, sr);  si = fmaf(v2, u2.x, si);
    sr = fmaf(v3, u3.y, sr);  si = fmaf(v3, u3.x, si);
}

// K2: one Euler step. 4 lanes per row WITHIN a warp (part = tid&3):
//  - main group `part` processed unconditionally (no cnt on critical path;
//    zero tail slots contribute exactly 0 via U[0]-broadcast gathers)
//  - overflow groups (slots >= 16) guarded by cnt, overlapped load
//  - reduction via shfl_xor (no smem, no __syncthreads)
template <bool FINAL>
__global__ __launch_bounds__(TB)
void step_kernel(int src, float* __restrict__ out) {
    const int tid  = blockIdx.x * TB + threadIdx.x;
    const int r    = tid >> 2;                       // row (8 rows per warp)
    const int part = tid & 3;                        // 0..3 within the row

    const float2* __restrict__ U = g_U[src];

    // Issue the main pair load first (address independent of any prior load).
    uint4 q = g_q4[r * 4 + part];                    // warp: 512B contiguous
    // cnt + "mine" overlap the main gathers.
    const unsigned cnt = g_cnt[r];
    float2 mine;
    if (part == 0) mine = U[r];

    float sr = 0.f, si = 0.f;
    accum4(q, U, sr, si);

    // Overflow (slots >= 16): lane `part` handles groups 4+part, 8+part, ...
    for (unsigned g = 4 + part; 4 * g < cnt; g += PARTS) {
        uint4 q2 = g_q4[4 * N_TOTAL + (g - 4) * N_TOTAL + r];
        accum4(q2, U, sr, si);
    }

    // Reduce across the 4 lanes of this row.
    sr += __shfl_xor_sync(0xFFFFFFFFu, sr, 1);
    sr += __shfl_xor_sync(0xFFFFFFFFu, sr, 2);
    si += __shfl_xor_sync(0xFFFFFFFFu, si, 1);
    si += __shfl_xor_sync(0xFFFFFFFFu, si, 2);

    if (part == 0) {
        float2 nxt = make_float2(mine.x - sr, mine.y + si);
        g_U[src ^ 1][r] = nxt;
        if (FINAL) {
            out[r]           = nxt.x;
            out[N_TOTAL + r] = nxt.y;
            g_cnt[r] = 0;                            // self-reset for replay
        }
    }
}

// ---------------------------------------------------------------------------
extern "C" void kernel_launch(void* const* d_in, const int* in_sizes, int n_in,
                              void* d_out, int out_size) {
    const float* A_vals  = (const float*)d_in[0];
    const int*   row_idx = (const int*)d_in[1];
    const int*   col_idx = (const int*)d_in[2];
    const float* Ur0     = (const float*)d_in[3];
    const float* Ui0     = (const float*)d_in[4];
    const float dz = 1.0f / (float)STEPS;

    fill_kernel<<<(NNZ / 8 + TB - 1) / TB, TB>>>(
        (const float4*)A_vals, (const int4*)row_idx, (const int4*)col_idx,
        Ur0, Ui0, dz);

    const int grid = (N_TOTAL * PARTS) / TB;         // 1024 blocks
    int src = 0;
    for (int s = 0; s < STEPS - 1; s++) {
        step_kernel<false><<<grid, TB>>>(src, nullptr);
        src ^= 1;
    }
    step_kernel<true><<<grid, TB>>>(src, (float*)d_out);
}